// round 1
// baseline (speedup 1.0000x reference)
#include <cuda_runtime.h>
#include <cuda_fp16.h>
#include <mma.h>

using namespace nvcuda;

// Problem dims
#define N_ROWS 32768     // b*h*w = 8*64*64
#define C_DIM  256
#define K_CODES 2048
#define CD     260       // c+4
#define H1W    288       // padded hidden1 width (>=260, mult of 32)
#define WNW    320       // padded wn width (>=260, mult of 64)

// Scratch (device globals -- allocation is forbidden)
__device__ __half  g_x16[N_ROWS * C_DIM];                 // fp16 x_flat (n,256)
__device__ float   g_xy[(size_t)N_ROWS * CD];             // fp32 [x|y]  (n,260)
__device__ float   g_rinv[N_ROWS];                        // 1/||x_row||
__device__ __half  g_mn16[K_CODES * C_DIM];               // normalized codebook fp16
__device__ __half  g_score[(size_t)N_ROWS * K_CODES];     // score, then p (in place)
__device__ float   g_sums[K_CODES * CD];
__device__ float   g_counts[K_CODES];
__device__ __half  g_wn[K_CODES * WNW];                   // l2norm(new_w), zero-padded
__device__ __half  g_h1[(size_t)N_ROWS * H1W];            // p @ wn  (n,288)
__device__ __half  g_h2[(size_t)N_ROWS * C_DIM];          // gelu(h1@w1+b1)
__device__ __half  g_w1[H1W * C_DIM];                     // w1 fp16, zero-padded rows
__device__ __half  g_w2[C_DIM * C_DIM];

// ---------------------------------------------------------------------------
// 1) NCHW -> (n, c) transpose; writes fp32 g_xy[:, :256] and fp16 g_x16
// grid (128, 8, 8), block (32, 8)
__global__ void prep_x_kernel(const float* __restrict__ x) {
    __shared__ float tile[32][33];
    int b = blockIdx.z, c0 = blockIdx.y * 32, s0 = blockIdx.x * 32;
    int tx = threadIdx.x, ty = threadIdx.y;
#pragma unroll
    for (int j = 0; j < 32; j += 8)
        tile[ty + j][tx] = x[(size_t)(b * 256 + c0 + ty + j) * 4096 + s0 + tx];
    __syncthreads();
#pragma unroll
    for (int j = 0; j < 32; j += 8) {
        int c = c0 + tx, s = s0 + ty + j, r = (b << 12) + s;
        float v = tile[tx][ty + j];
        g_xy[(size_t)r * CD + c] = v;
        g_x16[r * C_DIM + c] = __float2half(v);
    }
}

// 2) append y into g_xy cols 256..259. grid 128, block 256
__global__ void prep_y_kernel(const float* __restrict__ y) {
    int t = blockIdx.x * blockDim.x + threadIdx.x;
    if (t >= N_ROWS) return;
    int b = t >> 12, s = t & 4095;
    float4 v;
    v.x = y[((b * 4 + 0) << 12) + s];
    v.y = y[((b * 4 + 1) << 12) + s];
    v.z = y[((b * 4 + 2) << 12) + s];
    v.w = y[((b * 4 + 3) << 12) + s];
    *(float4*)&g_xy[(size_t)t * CD + 256] = v;
}

// 3) zero sums/counts, convert w1/w2 to fp16 (w1 zero-padded to 288 rows)
__global__ void prep_misc_kernel(const float* __restrict__ w1,
                                 const float* __restrict__ w2) {
    int t = blockIdx.x * blockDim.x + threadIdx.x;
    int nthr = gridDim.x * blockDim.x;
    for (int i = t; i < K_CODES * CD; i += nthr) g_sums[i] = 0.f;
    for (int i = t; i < K_CODES; i += nthr) g_counts[i] = 0.f;
    for (int i = t; i < H1W * C_DIM; i += nthr) {
        int row = i >> 8;
        g_w1[i] = __float2half(row < CD ? w1[(row << 8) + (i & 255)] : 0.f);
    }
    for (int i = t; i < C_DIM * C_DIM; i += nthr) g_w2[i] = __float2half(w2[i]);
}

// 4) normalize codebook feature rows (first 256 cols). warp per row.
__global__ void prep_mn_kernel(const float* __restrict__ fw) {
    int wid = threadIdx.x >> 5, lane = threadIdx.x & 31;
    int k = blockIdx.x * 8 + wid;
    if (k >= K_CODES) return;
    const float* p = fw + (size_t)k * CD;
    float v[8], s = 0.f;
#pragma unroll
    for (int j = 0; j < 8; j++) { v[j] = p[lane + j * 32]; s += v[j] * v[j]; }
#pragma unroll
    for (int o = 16; o; o >>= 1) s += __shfl_xor_sync(0xffffffffu, s, o);
    float ri = 1.0f / fmaxf(sqrtf(s), 1e-12f);
#pragma unroll
    for (int j = 0; j < 8; j++)
        g_mn16[k * C_DIM + lane + j * 32] = __float2half(v[j] * ri);
}

// 5) 1/||x_row||. warp per row.
__global__ void rownorm_kernel() {
    int wid = threadIdx.x >> 5, lane = threadIdx.x & 31;
    int r = blockIdx.x * 8 + wid;
    if (r >= N_ROWS) return;
    const float* p = g_xy + (size_t)r * CD;
    float s = 0.f;
#pragma unroll
    for (int j = 0; j < 8; j++) { float v = p[lane + j * 32]; s += v * v; }
#pragma unroll
    for (int o = 16; o; o >>= 1) s += __shfl_xor_sync(0xffffffffu, s, o);
    if (lane == 0) g_rinv[r] = 1.0f / fmaxf(sqrtf(s), 1e-12f);
}

// ---------------------------------------------------------------------------
// row kernel: max/argmax (first-index ties), softmax p (fp16, in place),
// atomic scatter of xy into sums/counts. One CTA (256 thr) per row.
__global__ __launch_bounds__(256) void rowproc_kernel() {
    __shared__ float sVal[256];
    __shared__ int   sIdx[256];
    int r = blockIdx.x, t = threadIdx.x;
    __half* sp = g_score + (size_t)r * K_CODES;

    __align__(16) __half h[8];
    *(uint4*)h = ((const uint4*)sp)[t];
    float f[8];
    float mx = -1e30f; int mi = 0;
#pragma unroll
    for (int i = 0; i < 8; i++) {
        f[i] = __half2float(h[i]);
        if (f[i] > mx) { mx = f[i]; mi = t * 8 + i; }
    }
    sVal[t] = mx; sIdx[t] = mi;
    __syncthreads();
    for (int o = 128; o; o >>= 1) {
        if (t < o) {
            float v2 = sVal[t + o]; int i2 = sIdx[t + o];
            if (v2 > sVal[t] || (v2 == sVal[t] && i2 < sIdx[t])) {
                sVal[t] = v2; sIdx[t] = i2;
            }
        }
        __syncthreads();
    }
    float rowmax = sVal[0];
    int ind = sIdx[0];
    __syncthreads();

    float e[8], s = 0.f;
#pragma unroll
    for (int i = 0; i < 8; i++) { e[i] = __expf(f[i] - rowmax); s += e[i]; }
    sVal[t] = s;
    __syncthreads();
    for (int o = 128; o; o >>= 1) {
        if (t < o) sVal[t] += sVal[t + o];
        __syncthreads();
    }
    float inv = 1.0f / sVal[0];
    __align__(16) __half o8[8];
#pragma unroll
    for (int i = 0; i < 8; i++) o8[i] = __float2half(e[i] * inv);
    ((uint4*)sp)[t] = *(uint4*)o8;

    const float* xyr = g_xy + (size_t)r * CD;
    for (int c = t; c < CD; c += 256)
        atomicAdd(&g_sums[ind * CD + c], xyr[c]);
    if (t == 0) atomicAdd(&g_counts[ind], 1.0f);
}

// EMA update + l2norm over 260 -> g_wn fp16 (zero-padded to 320). CTA per row.
__global__ __launch_bounds__(256) void neww_kernel(const float* __restrict__ fw) {
    __shared__ float red[256];
    int k = blockIdx.x, t = threadIdx.x;
    float denom = 1.0f / (g_counts[k] + 1e-6f);
    float v0, v1 = 0.f;
    {
        float a = fw[(size_t)k * CD + t];
        float sm = g_sums[k * CD + t];
        v0 = a * 0.999f + 0.001f * sm * denom;
    }
    if (t < 4) {
        int j = 256 + t;
        float a = fw[(size_t)k * CD + j];
        float sm = g_sums[k * CD + j];
        v1 = a * 0.999f + 0.001f * sm * denom;
    }
    red[t] = v0 * v0 + v1 * v1;
    __syncthreads();
    for (int o = 128; o; o >>= 1) {
        if (t < o) red[t] += red[t + o];
        __syncthreads();
    }
    float ri = 1.0f / fmaxf(sqrtf(red[0]), 1e-12f);
    g_wn[k * WNW + t] = __float2half(v0 * ri);
    if (t < 4)  g_wn[k * WNW + 256 + t] = __float2half(v1 * ri);
    if (t < 60) g_wn[k * WNW + 260 + t] = __float2half(0.f);
}

// ---------------------------------------------------------------------------
__device__ __forceinline__ float gelu_tanh(float v) {
    float u = 0.7978845608028654f * (v + 0.044715f * v * v * v);
    return 0.5f * v * (1.0f + tanhf(u));
}

// Unified wmma GEMM, 128 x BN tile, BK=32, 8 warps (4x2), warp tile 32 x BN/2.
// MODE 1: score = x16 @ mn^T      * rinv[row]    -> g_score fp16 (ld 2048)
// MODE 2: h1    = p @ wn                          -> g_h1    fp16 (ld 288, pred)
// MODE 3: h2    = gelu(h1 @ w1 + b1)              -> g_h2    fp16 (ld 256)
// MODE 4: out   = h2 @ w2 + b2                    -> NCHW fp32
template <int MODE, int BN>
__global__ __launch_bounds__(256) void gemm_kernel(const float* __restrict__ bias,
                                                   float* __restrict__ out4) {
    constexpr int BK = 32;
    constexpr int WN = BN / 32;
    __shared__ __half As[128][BK + 8];
    __shared__ __half Bs[BK][BN + 8];
    __shared__ float  Cst[8][256];

    const __half* A;  int lda;  const __half* Bg;  int ldb;  int K;
    if (MODE == 1)      { A = g_x16;   lda = 256;  Bg = g_mn16; ldb = 256; K = 256;  }
    else if (MODE == 2) { A = g_score; lda = 2048; Bg = g_wn;   ldb = WNW; K = 2048; }
    else if (MODE == 3) { A = g_h1;    lda = H1W;  Bg = g_w1;   ldb = 256; K = H1W;  }
    else                { A = g_h2;    lda = 256;  Bg = g_w2;   ldb = 256; K = 256;  }

    int tid = threadIdx.x;
    int wid = tid >> 5, lane = tid & 31;
    int warpRow = wid >> 1, warpCol = wid & 1;
    int r0 = blockIdx.x * 128;
    int n0 = blockIdx.y * BN;

    wmma::fragment<wmma::accumulator, 16, 16, 16, float> acc[2][WN];
#pragma unroll
    for (int m = 0; m < 2; m++)
#pragma unroll
        for (int n = 0; n < WN; n++) wmma::fill_fragment(acc[m][n], 0.0f);

    for (int k0 = 0; k0 < K; k0 += BK) {
#pragma unroll
        for (int v = tid; v < 128 * 4; v += 256) {
            int row = v >> 2, kk = (v & 3) << 3;
            *(uint4*)&As[row][kk] =
                *(const uint4*)&A[(size_t)(r0 + row) * lda + k0 + kk];
        }
        if (MODE == 1) {
            // B global is n-major (mn rows): transpose into k-major smem
#pragma unroll
            for (int e = tid; e < 16 * BN; e += 256) {
                int k2 = e & 15, n = e >> 4;
                __half2 p = *(const __half2*)&Bg[(size_t)(n0 + n) * ldb + k0 + k2 * 2];
                Bs[k2 * 2][n]     = __low2half(p);
                Bs[k2 * 2 + 1][n] = __high2half(p);
            }
        } else {
#pragma unroll
            for (int v = tid; v < BK * BN / 8; v += 256) {
                int k = v / (BN / 8), n = (v % (BN / 8)) * 8;
                *(uint4*)&Bs[k][n] =
                    *(const uint4*)&Bg[(size_t)(k0 + k) * ldb + n0 + n];
            }
        }
        __syncthreads();
#pragma unroll
        for (int kk = 0; kk < 2; kk++) {
            wmma::fragment<wmma::matrix_a, 16, 16, 16, __half, wmma::row_major> af[2];
            wmma::fragment<wmma::matrix_b, 16, 16, 16, __half, wmma::row_major> bf[WN];
#pragma unroll
            for (int m = 0; m < 2; m++)
                wmma::load_matrix_sync(af[m], &As[warpRow * 32 + m * 16][kk * 16], BK + 8);
#pragma unroll
            for (int n = 0; n < WN; n++)
                wmma::load_matrix_sync(bf[n], &Bs[kk * 16][warpCol * (BN / 2) + n * 16], BN + 8);
#pragma unroll
            for (int m = 0; m < 2; m++)
#pragma unroll
                for (int n = 0; n < WN; n++)
                    wmma::mma_sync(acc[m][n], af[m], bf[n], acc[m][n]);
        }
        __syncthreads();
    }

    // epilogue, one 16x16 fragment at a time via per-warp smem staging
#pragma unroll
    for (int m = 0; m < 2; m++)
#pragma unroll
        for (int n = 0; n < WN; n++) {
            float* cs = Cst[wid];
            wmma::store_matrix_sync(cs, acc[m][n], 16, wmma::mem_row_major);
            __syncwarp();
            int gr = r0 + warpRow * 32 + m * 16;
            int gc = n0 + warpCol * (BN / 2) + n * 16;
            if (MODE == 4) {
                int fc = lane >> 1;
                int frb = (lane & 1) * 8;
                float bv = bias[gc + fc];
#pragma unroll
                for (int i = 0; i < 8; i++) {
                    int fr = frb + i;
                    int r = gr + fr;
                    float val = cs[fr * 16 + fc] + bv;
                    out4[(size_t)((r >> 12) * 256 + gc + fc) * 4096 + (r & 4095)] = val;
                }
            } else if (!(MODE == 2 && gc >= H1W)) {
                int fr = lane >> 1;
                int fcb = (lane & 1) * 8;
                int r = gr + fr;
                __half* outp;  int ldc;
                if (MODE == 1) { outp = g_score; ldc = 2048; }
                else if (MODE == 2) { outp = g_h1; ldc = H1W; }
                else { outp = g_h2; ldc = 256; }
                float scale = (MODE == 1) ? g_rinv[r] : 1.0f;
                __align__(16) __half tmp[8];
#pragma unroll
                for (int i = 0; i < 8; i++) {
                    float val = cs[fr * 16 + fcb + i];
                    if (MODE == 1) val *= scale;
                    if (MODE == 3) val = gelu_tanh(val + bias[gc + fcb + i]);
                    tmp[i] = __float2half(val);
                }
                *(uint4*)&outp[(size_t)r * ldc + gc + fcb] = *(uint4*)tmp;
            }
            __syncwarp();
        }
}

// ---------------------------------------------------------------------------
extern "C" void kernel_launch(void* const* d_in, const int* in_sizes, int n_in,
                              void* d_out, int out_size) {
    const float* x  = (const float*)d_in[0];
    const float* y  = (const float*)d_in[1];
    const float* fw = (const float*)d_in[2];
    const float* w1 = (const float*)d_in[3];
    const float* b1 = (const float*)d_in[4];
    const float* w2 = (const float*)d_in[5];
    const float* b2 = (const float*)d_in[6];
    float* out = (float*)d_out;

    prep_x_kernel<<<dim3(128, 8, 8), dim3(32, 8)>>>(x);
    prep_y_kernel<<<128, 256>>>(y);
    prep_misc_kernel<<<512, 256>>>(w1, w2);
    prep_mn_kernel<<<256, 256>>>(fw);
    rownorm_kernel<<<4096, 256>>>();

    gemm_kernel<1, 128><<<dim3(256, 16), 256>>>(nullptr, nullptr);   // score
    rowproc_kernel<<<32768, 256>>>();                                // softmax+scatter
    neww_kernel<<<2048, 256>>>(fw);                                  // EMA + norm
    gemm_kernel<2, 64><<<dim3(256, 5), 256>>>(nullptr, nullptr);     // p @ wn
    gemm_kernel<3, 64><<<dim3(256, 4), 256>>>(b1, nullptr);          // MLP layer 1
    gemm_kernel<4, 64><<<dim3(256, 4), 256>>>(b2, out);              // MLP layer 2 + NCHW
}

// round 4
// speedup vs baseline: 1.2949x; 1.2949x over previous
#include <cuda_runtime.h>
#include <cuda_fp16.h>
#include <mma.h>
#include <cstdint>

using namespace nvcuda;

// ---------------------------------------------------------------------------
// Problem dims
#define N_ROWS 32768     // b*h*w = 8*64*64
#define C_DIM  256
#define K_CODES 2048
#define CD     260       // c+4
#define H1W    320       // padded hidden1 / wn width

// Scratch (device globals -- allocation is forbidden)
__device__ __half  g_x16[N_ROWS * C_DIM];                 // fp16 x_flat (n,256)
__device__ float   g_rinv[N_ROWS];                        // 1/||x_row||
__device__ __half  g_mn16[K_CODES * C_DIM];               // normalized codebook fp16
__device__ __half  g_score[(size_t)N_ROWS * K_CODES];     // score, then p (in place)
__device__ float   g_sums[K_CODES * CD];
__device__ float   g_counts[K_CODES];
__device__ __half  g_wn[K_CODES * H1W];                   // l2norm(new_w) row-major
__device__ __half  g_wnT[H1W * K_CODES];                  // transposed [320][2048]
__device__ __half  g_h1[(size_t)N_ROWS * H1W];            // p @ wn  (n,320)
__device__ __half  g_h2[(size_t)N_ROWS * C_DIM];          // gelu(h1@w1+b1)
__device__ __half  g_w1T[C_DIM * H1W];                    // w1^T fp16 [256][320] pad
__device__ __half  g_w2T[C_DIM * C_DIM];                  // w2^T fp16

// ---------------------------------------------------------------------------
#define CP_ASYNC16(dst, src) \
    asm volatile("cp.async.cg.shared.global [%0], [%1], 16;\n" \
                 :: "r"(dst), "l"(src) : "memory")
#define CP_COMMIT asm volatile("cp.async.commit_group;\n" ::: "memory")
#define CP_WAIT1  asm volatile("cp.async.wait_group 1;\n" ::: "memory")
#define CP_WAIT0  asm volatile("cp.async.wait_group 0;\n" ::: "memory")

__device__ __forceinline__ uint32_t smem_u32(const void* p) {
    uint32_t a;
    asm("{ .reg .u64 t; cvta.to.shared.u64 t, %1; cvt.u32.u64 %0, t; }"
        : "=r"(a) : "l"(p));
    return a;
}

__device__ __forceinline__ float gelu_tanh(float v) {
    float u = 0.7978845608028654f * (v + 0.044715f * v * v * v);
    return 0.5f * v * (1.0f + tanhf(u));
}

// ---------------------------------------------------------------------------
// prep: zero sums/counts, build transposed fp16 weights
__global__ void prep_misc_kernel(const float* __restrict__ w1,
                                 const float* __restrict__ w2) {
    int t = blockIdx.x * blockDim.x + threadIdx.x;
    int nthr = gridDim.x * blockDim.x;
    for (int i = t; i < K_CODES * CD; i += nthr) g_sums[i] = 0.f;
    for (int i = t; i < K_CODES; i += nthr) g_counts[i] = 0.f;
    for (int i = t; i < C_DIM * H1W; i += nthr) {
        int j = i / H1W, k = i % H1W;
        g_w1T[i] = __float2half(k < CD ? w1[k * C_DIM + j] : 0.f);
    }
    for (int i = t; i < C_DIM * C_DIM; i += nthr) {
        int j = i >> 8, k = i & 255;
        g_w2T[i] = __float2half(w2[k * C_DIM + j]);
    }
}

// NCHW -> (n,256) fp16 transpose. grid (128, 8, 8), block (32, 8)
__global__ void prep_x_kernel(const float* __restrict__ x) {
    __shared__ float tile[32][33];
    int b = blockIdx.z, c0 = blockIdx.y * 32, s0 = blockIdx.x * 32;
    int tx = threadIdx.x, ty = threadIdx.y;
#pragma unroll
    for (int j = 0; j < 32; j += 8)
        tile[ty + j][tx] = x[(size_t)(b * 256 + c0 + ty + j) * 4096 + s0 + tx];
    __syncthreads();
#pragma unroll
    for (int j = 0; j < 32; j += 8) {
        int c = c0 + tx, s = s0 + ty + j, r = (b << 12) + s;
        g_x16[r * C_DIM + c] = __float2half(tile[tx][ty + j]);
    }
}

// normalize codebook feature rows -> g_mn16. warp per row.
__global__ void prep_mn_kernel(const float* __restrict__ fw) {
    int wid = threadIdx.x >> 5, lane = threadIdx.x & 31;
    int k = blockIdx.x * 8 + wid;
    if (k >= K_CODES) return;
    const float* p = fw + (size_t)k * CD;
    float v[8], s = 0.f;
#pragma unroll
    for (int j = 0; j < 8; j++) { v[j] = p[lane + j * 32]; s += v[j] * v[j]; }
#pragma unroll
    for (int o = 16; o; o >>= 1) s += __shfl_xor_sync(0xffffffffu, s, o);
    float ri = 1.0f / fmaxf(sqrtf(s), 1e-12f);
#pragma unroll
    for (int j = 0; j < 8; j++)
        g_mn16[k * C_DIM + lane + j * 32] = __float2half(v[j] * ri);
}

// 1/||x_row|| from fp16 x. warp per row.
__global__ void rownorm_kernel() {
    int wid = threadIdx.x >> 5, lane = threadIdx.x & 31;
    int r = blockIdx.x * 8 + wid;
    if (r >= N_ROWS) return;
    uint4 u = ((const uint4*)(g_x16 + (size_t)r * C_DIM))[lane];
    const __half2* h2 = (const __half2*)&u;
    float s = 0.f;
#pragma unroll
    for (int j = 0; j < 4; j++) {
        float2 f = __half22float2(h2[j]);
        s += f.x * f.x + f.y * f.y;
    }
#pragma unroll
    for (int o = 16; o; o >>= 1) s += __shfl_xor_sync(0xffffffffu, s, o);
    if (lane == 0) g_rinv[r] = 1.0f / fmaxf(sqrtf(s), 1e-12f);
}

// ---------------------------------------------------------------------------
// HMMA GEMM: CTA tile 128 x NT, BK=64, cp.async double-buffered.
// A row-major [M][K]; B [N][K] (k-contiguous) -> wmma col_major fragments.
// MODE 1: score = x16 @ mn^T  (*rinv)   -> g_score fp16
// MODE 2: h1    = p @ wnT^T             -> g_h1 fp16
// MODE 3: h2    = gelu(h1 @ w1T^T + b1) -> g_h2 fp16
// MODE 4: out   = h2 @ w2T^T + b2       -> NCHW fp32 (coalesced via col-major C)
template <int MODE, int NT, int N0OFF>
__global__ __launch_bounds__(256) void tc_gemm(const float* __restrict__ bias,
                                               float* __restrict__ out4) {
    constexpr int K  = (MODE == 1) ? 256 : (MODE == 2) ? 2048 : (MODE == 3) ? 320 : 256;
    constexpr int NIT = K / 64;
    constexpr int SA = 72;                       // smem k-stride (halves)
    constexpr int ASZ = 128 * SA;                // halves per A stage
    constexpr int BSZ = NT * SA;
    constexpr int STG = ASZ + BSZ;
    constexpr int WNT = NT / 2;                  // per-warp N (warps 4x2)
    constexpr int NF  = WNT / 16;                // b-frags per warp
    constexpr int CST = NT == 128 ? 132 : 68;    // C staging stride (floats)

    extern __shared__ __half sm[];

    const __half* Ag; const __half* Bg;
    if constexpr (MODE == 1) { Ag = g_x16;   Bg = g_mn16; }
    else if constexpr (MODE == 2) { Ag = g_score; Bg = g_wnT; }
    else if constexpr (MODE == 3) { Ag = g_h1;    Bg = g_w1T; }
    else { Ag = g_h2; Bg = g_w2T; }

    int tid = threadIdx.x, w = tid >> 5, lane = tid & 31;
    int wm = w & 3, wn = w >> 2;                 // warp grid 4(M) x 2(N)
    int r0 = blockIdx.x * 128;
    int n0 = N0OFF + blockIdx.y * NT;

    // ---- async stage loader ----
    auto load_stage = [&](int c, int s) {
        uint32_t abase = smem_u32(sm + s * STG);
        uint32_t bbase = abase + ASZ * 2;
        const __half* Ac = Ag + (size_t)r0 * K + c * 64;
        const __half* Bc = Bg + (size_t)n0 * K + c * 64;
#pragma unroll
        for (int v = tid; v < 128 * 8; v += 256) {
            int row = v >> 3, kv = v & 7;
            CP_ASYNC16(abase + (row * SA + kv * 8) * 2,
                       Ac + (size_t)row * K + kv * 8);
        }
#pragma unroll
        for (int v = tid; v < NT * 8; v += 256) {
            int row = v >> 3, kv = v & 7;
            CP_ASYNC16(bbase + (row * SA + kv * 8) * 2,
                       Bc + (size_t)row * K + kv * 8);
        }
    };

    wmma::fragment<wmma::accumulator, 16, 16, 16, float> acc[2][NF];
#pragma unroll
    for (int m = 0; m < 2; m++)
#pragma unroll
        for (int n = 0; n < NF; n++) wmma::fill_fragment(acc[m][n], 0.0f);

    load_stage(0, 0); CP_COMMIT;

    for (int it = 0; it < NIT; it++) {
        int s = it & 1;
        if (it + 1 < NIT) { load_stage(it + 1, s ^ 1); CP_COMMIT; CP_WAIT1; }
        else              { CP_WAIT0; }
        __syncthreads();
        const __half* As_ = sm + s * STG;
        const __half* Bs_ = As_ + ASZ;
#pragma unroll
        for (int kk = 0; kk < 4; kk++) {
            wmma::fragment<wmma::matrix_a, 16, 16, 16, __half, wmma::row_major> af[2];
            wmma::fragment<wmma::matrix_b, 16, 16, 16, __half, wmma::col_major> bf[NF];
#pragma unroll
            for (int m = 0; m < 2; m++)
                wmma::load_matrix_sync(af[m], As_ + (wm * 32 + m * 16) * SA + kk * 16, SA);
#pragma unroll
            for (int n = 0; n < NF; n++)
                wmma::load_matrix_sync(bf[n], Bs_ + (wn * WNT + n * 16) * SA + kk * 16, SA);
#pragma unroll
            for (int m = 0; m < 2; m++)
#pragma unroll
                for (int n = 0; n < NF; n++)
                    wmma::mma_sync(acc[m][n], af[m], bf[n], acc[m][n]);
        }
        __syncthreads();
    }

    // ---- epilogue: stage C in smem (reuses pipeline smem) ----
    float* Cs = (float*)sm;
#pragma unroll
    for (int m = 0; m < 2; m++)
#pragma unroll
        for (int n = 0; n < NF; n++) {
            int lr = wm * 32 + m * 16, lc = wn * WNT + n * 16;
            if constexpr (MODE == 4)
                wmma::store_matrix_sync(Cs + lc * CST + lr, acc[m][n], CST,
                                        wmma::mem_col_major);
            else
                wmma::store_matrix_sync(Cs + lr * CST + lc, acc[m][n], CST,
                                        wmma::mem_row_major);
        }
    __syncthreads();

    if constexpr (MODE == 4) {
        // Cs[col][row]; thread -> 8 consecutive rows of one col: coalesced NCHW
        int cb = tid >> 4;                 // 0..15
        int rf = (tid & 15) * 8;
        int b = r0 >> 12, s0 = r0 & 4095;
#pragma unroll
        for (int pass = 0; pass < 8; pass++) {
            int c = cb + pass * 16, gc = n0 + c;
            float bv = bias[gc];
            float* op = out4 + (size_t)(b * 256 + gc) * 4096 + s0 + rf;
#pragma unroll
            for (int i = 0; i < 8; i++) op[i] = Cs[c * CST + rf + i] + bv;
        }
    } else {
        constexpr int CPT = NT / 8;        // threads per row
        constexpr int RPP = 256 / CPT;     // rows per pass
        int c0 = (tid % CPT) * 8;
        int rb = tid / CPT;
#pragma unroll
        for (int pass = 0; pass < 128 / RPP; pass++) {
            int row = rb + pass * RPP, gr = r0 + row;
            float scale = (MODE == 1) ? g_rinv[gr] : 1.0f;
            __align__(16) __half hh[8];
#pragma unroll
            for (int i = 0; i < 8; i++) {
                float v = Cs[row * CST + c0 + i];
                if constexpr (MODE == 1) v *= scale;
                if constexpr (MODE == 3) v = gelu_tanh(v + bias[n0 + c0 + i]);
                hh[i] = __float2half(v);
            }
            __half* op;
            if constexpr (MODE == 1) op = g_score + (size_t)gr * 2048 + n0 + c0;
            else if constexpr (MODE == 2) op = g_h1 + (size_t)gr * H1W + n0 + c0;
            else op = g_h2 + (size_t)gr * 256 + n0 + c0;
            *(uint4*)op = *(uint4*)hh;
        }
    }
}

// ---------------------------------------------------------------------------
// row kernel: argmax (first-index ties), softmax p (fp16, in place),
// atomic scatter of [x16|y] into sums/counts. One CTA (256 thr) per row.
__global__ __launch_bounds__(256) void rowproc_kernel(const float* __restrict__ y) {
    __shared__ float sVal[256];
    __shared__ int   sIdx[256];
    int r = blockIdx.x, t = threadIdx.x;
    __half* sp = g_score + (size_t)r * K_CODES;

    __align__(16) __half h[8];
    *(uint4*)h = ((const uint4*)sp)[t];
    float f[8];
    float mx = -1e30f; int mi = 0;
#pragma unroll
    for (int i = 0; i < 8; i++) {
        f[i] = __half2float(h[i]);
        if (f[i] > mx) { mx = f[i]; mi = t * 8 + i; }
    }
    sVal[t] = mx; sIdx[t] = mi;
    __syncthreads();
    for (int o = 128; o; o >>= 1) {
        if (t < o) {
            float v2 = sVal[t + o]; int i2 = sIdx[t + o];
            if (v2 > sVal[t] || (v2 == sVal[t] && i2 < sIdx[t])) {
                sVal[t] = v2; sIdx[t] = i2;
            }
        }
        __syncthreads();
    }
    float rowmax = sVal[0];
    int ind = sIdx[0];
    __syncthreads();

    float e[8], s = 0.f;
#pragma unroll
    for (int i = 0; i < 8; i++) { e[i] = __expf(f[i] - rowmax); s += e[i]; }
    sVal[t] = s;
    __syncthreads();
    for (int o = 128; o; o >>= 1) {
        if (t < o) sVal[t] += sVal[t + o];
        __syncthreads();
    }
    float inv = 1.0f / sVal[0];
    __align__(16) __half o8[8];
#pragma unroll
    for (int i = 0; i < 8; i++) o8[i] = __float2half(e[i] * inv);
    ((uint4*)sp)[t] = *(uint4*)o8;

    float xv = __half2float(g_x16[(size_t)r * C_DIM + t]);
    atomicAdd(&g_sums[ind * CD + t], xv);
    if (t < 4) {
        int b = r >> 12, sidx = r & 4095;
        atomicAdd(&g_sums[ind * CD + 256 + t], y[((b * 4 + t) << 12) + sidx]);
    }
    if (t == 0) atomicAdd(&g_counts[ind], 1.0f);
}

// EMA update + l2norm over 260 -> g_wn fp16 (row-major, zero-padded). CTA/row.
__global__ __launch_bounds__(256) void neww_kernel(const float* __restrict__ fw) {
    __shared__ float red[256];
    int k = blockIdx.x, t = threadIdx.x;
    float denom = 1.0f / (g_counts[k] + 1e-6f);
    float v0, v1 = 0.f;
    {
        float a = fw[(size_t)k * CD + t];
        float sm2 = g_sums[k * CD + t];
        v0 = a * 0.999f + 0.001f * sm2 * denom;
    }
    if (t < 4) {
        int j = 256 + t;
        float a = fw[(size_t)k * CD + j];
        float sm2 = g_sums[k * CD + j];
        v1 = a * 0.999f + 0.001f * sm2 * denom;
    }
    red[t] = v0 * v0 + v1 * v1;
    __syncthreads();
    for (int o = 128; o; o >>= 1) {
        if (t < o) red[t] += red[t + o];
        __syncthreads();
    }
    float ri = 1.0f / fmaxf(sqrtf(red[0]), 1e-12f);
    g_wn[k * H1W + t] = __float2half(v0 * ri);
    if (t < 4)  g_wn[k * H1W + 256 + t] = __float2half(v1 * ri);
    if (t < 60) g_wn[k * H1W + 260 + t] = __float2half(0.f);
}

// transpose g_wn [2048][320] -> g_wnT [320][2048]. grid (64,10), block (32,8)
__global__ void wnT_kernel() {
    __shared__ __half tile[32][33];
    int k0 = blockIdx.x * 32, j0 = blockIdx.y * 32;
    int tx = threadIdx.x, ty = threadIdx.y;
#pragma unroll
    for (int jj = 0; jj < 32; jj += 8)
        tile[ty + jj][tx] = g_wn[(k0 + ty + jj) * H1W + j0 + tx];
    __syncthreads();
#pragma unroll
    for (int jj = 0; jj < 32; jj += 8)
        g_wnT[(size_t)(j0 + ty + jj) * K_CODES + k0 + tx] = tile[tx][ty + jj];
}

// ---------------------------------------------------------------------------
extern "C" void kernel_launch(void* const* d_in, const int* in_sizes, int n_in,
                              void* d_out, int out_size) {
    const float* x  = (const float*)d_in[0];
    const float* y  = (const float*)d_in[1];
    const float* fw = (const float*)d_in[2];
    const float* w1 = (const float*)d_in[3];
    const float* b1 = (const float*)d_in[4];
    const float* w2 = (const float*)d_in[5];
    const float* b2 = (const float*)d_in[6];
    float* out = (float*)d_out;

    constexpr int SM128 = (128 + 128) * 72 * 2 * 2;   // 73728
    constexpr int SM64  = (128 + 64) * 72 * 2 * 2;    // 55296
    cudaFuncSetAttribute(tc_gemm<1,128,0>, cudaFuncAttributeMaxDynamicSharedMemorySize, SM128);
    cudaFuncSetAttribute(tc_gemm<2,128,0>, cudaFuncAttributeMaxDynamicSharedMemorySize, SM128);
    cudaFuncSetAttribute(tc_gemm<2,64,256>, cudaFuncAttributeMaxDynamicSharedMemorySize, SM64);
    cudaFuncSetAttribute(tc_gemm<3,128,0>, cudaFuncAttributeMaxDynamicSharedMemorySize, SM128);
    cudaFuncSetAttribute(tc_gemm<4,128,0>, cudaFuncAttributeMaxDynamicSharedMemorySize, SM128);

    prep_misc_kernel<<<512, 256>>>(w1, w2);
    prep_x_kernel<<<dim3(128, 8, 8), dim3(32, 8)>>>(x);
    prep_mn_kernel<<<256, 256>>>(fw);
    rownorm_kernel<<<4096, 256>>>();

    tc_gemm<1,128,0><<<dim3(256, 16), 256, SM128>>>(nullptr, nullptr);  // score
    rowproc_kernel<<<32768, 256>>>(y);                                  // softmax+scatter
    neww_kernel<<<2048, 256>>>(fw);                                     // EMA + norm
    wnT_kernel<<<dim3(64, 10), dim3(32, 8)>>>();                        // transpose wn
    tc_gemm<2,128,0><<<dim3(256, 2), 256, SM128>>>(nullptr, nullptr);   // p @ wn [0:256)
    tc_gemm<2,64,256><<<dim3(256, 1), 256, SM64>>>(nullptr, nullptr);   // p @ wn [256:320)
    tc_gemm<3,128,0><<<dim3(256, 2), 256, SM128>>>(b1, nullptr);        // MLP layer 1
    tc_gemm<4,128,0><<<dim3(256, 2), 256, SM128>>>(b2, out);            // MLP layer 2
}